// round 8
// baseline (speedup 1.0000x reference)
#include <cuda_runtime.h>
#include <cuda_fp16.h>

// ROIAlign(7x7, sr=2) + global avg pool, separable-weight formulation.
// out[roi,ch] = sum_r a[r] * sum_c b[c] * F[bi,ch,r,c]; a/b are the y/x
// bilinear weight marginals (b pre-scaled by 1/196).
//
// R7: L1-pipe diet + occupancy. Flat exact-cover work list where the row
// weight a[r] is PREMULTIPLIED into each entry's column-weight float4, so
// the inner loop reads only {int byte-offset, float4 weights} from shared
// (20B/lane vs 24B) and drops 8 FMAs/iter. 8 channels per warp via
// constant 512KB immediate offsets. launch_bounds(256,4): 64 regs exactly
// fills the RF at 4 blocks/SM -> ~33% more resident warps.

#define NTHREADS 256
#define NWARPS   8
#define C_CH     256
#define HW       128
#define CH_STRIDE_B (HW * HW * 4)            // 64 KB per channel
#define MAX_T    400                          // >= 28 rows * 14 chunks

__global__ __launch_bounds__(NTHREADS, 4)
void roi_align_pool_kernel(const float* __restrict__ feat,
                           const float* __restrict__ rois,
                           float* __restrict__ out,
                           int n_rois)
{
    __shared__ float  a_sh[HW];        // row (H) weights
    __shared__ float  b_sh[192];       // col (W) weights (x 1/196), zero-padded
    __shared__ float2 rows_sh[64];     // compacted (weight, row byte-offset)
    __shared__ int    off_sh[MAX_T];   // flat: full byte-offset
    __shared__ float4 bwt_sh[MAX_T];   // flat: a[r]-premultiplied col weights
    __shared__ int rlo_s, rhi_s, clo_s, chi_s, bi_s, nr_s, T_s, base_s, nch_s;

    const int roi = blockIdx.x;
    const int tid = threadIdx.x;

    if (tid == 0) {
        rlo_s = 1 << 30; rhi_s = -1;
        clo_s = 1 << 30; chi_s = -1;
        bi_s = (int)rois[roi * 6 + 0];
        if (blockIdx.y == 0)  // second output: gt = rois[:,1]
            out[(size_t)n_rois * C_CH + roi] = rois[roi * 6 + 1];
    }
    if (tid < 192) {
        if (tid < HW) a_sh[tid] = 0.f;
        b_sh[tid] = 0.f;
    }
    __syncthreads();

    // One warp builds the separable weight vectors.
    if (tid < 32) {
        const bool isY = (tid < 14);
        const bool isX = (tid >= 16 && tid < 30);
        if (isY || isX) {
            const int s = isY ? tid : tid - 16;
            const float cx = rois[roi * 6 + 2];
            const float cy = rois[roi * 6 + 3];
            const float w  = rois[roi * 6 + 4];
            const float h  = rois[roi * 6 + 5];
            // Reference rounds the scaled corners through fp16.
            const float x1 = __half2float(__float2half_rn((cx - 0.5f * w) * 128.f));
            const float x2 = __half2float(__float2half_rn((cx + 0.5f * w) * 128.f));
            const float y1 = __half2float(__float2half_rn((cy - 0.5f * h) * 128.f));
            const float y2 = __half2float(__float2half_rn((cy + 0.5f * h) * 128.f));
            const float rw = fmaxf(x2 - x1, 1.f);
            const float rh = fmaxf(y2 - y1, 1.f);

            const float off   = 0.25f + 0.5f * (float)s;   // p + (sub+0.5)/2
            const float start = isY ? y1 : x1;
            const float ext   = isY ? rh : rw;
            const float coord = start + off * (ext / 7.f);

            if (coord > -1.f && coord < 128.f) {
                const float cl = fminf(fmaxf(coord, 0.f), 127.f);
                const int   i0 = (int)floorf(cl);
                const int   i1 = min(i0 + 1, HW - 1);
                const float l  = cl - (float)i0;
                const float hi = 1.f - l;
                if (isY) {
                    atomicAdd(&a_sh[i0], hi);
                    atomicAdd(&a_sh[i1], l);
                    atomicMin(&rlo_s, i0);
                    atomicMax(&rhi_s, i1);
                } else {
                    const float inv = 1.f / 196.f;  // fold in the mean
                    atomicAdd(&b_sh[i0], hi * inv);
                    atomicAdd(&b_sh[i1], l * inv);
                    atomicMin(&clo_s, i0);
                    atomicMax(&chi_s, i1);
                }
            }
        }
    }
    __syncthreads();

    // Compact nonzero rows; compute flat-list geometry.
    if (tid == 0) {
        int n = 0;
        int base = 0, nch = 0;
        if (rhi_s >= rlo_s && chi_s >= clo_s) {
            for (int r = rlo_s; r <= rhi_s; ++r) {
                const float w = a_sh[r];
                if (w != 0.f)
                    rows_sh[n++] = make_float2(w, __int_as_float(r * HW * 4));
            }
            base = clo_s & ~3;
            nch  = ((chi_s - base) >> 2) + 1;   // exact chunk count (<=14)
        }
        nr_s = n; base_s = base; nch_s = nch;
        T_s = n * nch;
    }
    __syncthreads();

    // Build the flat work list in parallel (row weight folded into bwt).
    const int T = T_s;
    {
        const int base = base_s, nch = nch_s;
        for (int t = tid; t < T; t += NTHREADS) {
            const int row = t / nch;
            const int c   = t - row * nch;
            const float2 rr = rows_sh[row];
            off_sh[t] = __float_as_int(rr.y) + base * 4 + 16 * c;
            const float4 b = *(const float4*)&b_sh[base + 4 * c];
            bwt_sh[t] = make_float4(rr.x * b.x, rr.x * b.y,
                                    rr.x * b.z, rr.x * b.w);
        }
    }
    __syncthreads();

    const int warp = tid >> 5;
    const int lane = tid & 31;

    const char* fb = (const char*)(feat + (size_t)bi_s * C_CH * (HW * HW));
    const int c0 = blockIdx.y * 64 + warp;    // warp's channels: c0 + 8k, k=0..7
    const char* cb = fb + (size_t)c0 * CH_STRIDE_B;

    float a0 = 0.f, a1 = 0.f, a2 = 0.f, a3 = 0.f;
    float a4 = 0.f, a5 = 0.f, a6 = 0.f, a7 = 0.f;
    #pragma unroll 1
    for (int t = lane; t < T; t += 32) {
        const int   o  = off_sh[t];
        const float4 bw = bwt_sh[t];
        const char* p = cb + o;
        const float4 f0 = *(const float4*)(p);
        const float4 f1 = *(const float4*)(p + 8  * CH_STRIDE_B);
        const float4 f2 = *(const float4*)(p + 16 * CH_STRIDE_B);
        const float4 f3 = *(const float4*)(p + 24 * CH_STRIDE_B);
        const float4 f4 = *(const float4*)(p + 32 * CH_STRIDE_B);
        const float4 f5 = *(const float4*)(p + 40 * CH_STRIDE_B);
        const float4 f6 = *(const float4*)(p + 48 * CH_STRIDE_B);
        const float4 f7 = *(const float4*)(p + 56 * CH_STRIDE_B);
        a0 = fmaf(bw.x, f0.x, a0); a0 = fmaf(bw.y, f0.y, a0);
        a0 = fmaf(bw.z, f0.z, a0); a0 = fmaf(bw.w, f0.w, a0);
        a1 = fmaf(bw.x, f1.x, a1); a1 = fmaf(bw.y, f1.y, a1);
        a1 = fmaf(bw.z, f1.z, a1); a1 = fmaf(bw.w, f1.w, a1);
        a2 = fmaf(bw.x, f2.x, a2); a2 = fmaf(bw.y, f2.y, a2);
        a2 = fmaf(bw.z, f2.z, a2); a2 = fmaf(bw.w, f2.w, a2);
        a3 = fmaf(bw.x, f3.x, a3); a3 = fmaf(bw.y, f3.y, a3);
        a3 = fmaf(bw.z, f3.z, a3); a3 = fmaf(bw.w, f3.w, a3);
        a4 = fmaf(bw.x, f4.x, a4); a4 = fmaf(bw.y, f4.y, a4);
        a4 = fmaf(bw.z, f4.z, a4); a4 = fmaf(bw.w, f4.w, a4);
        a5 = fmaf(bw.x, f5.x, a5); a5 = fmaf(bw.y, f5.y, a5);
        a5 = fmaf(bw.z, f5.z, a5); a5 = fmaf(bw.w, f5.w, a5);
        a6 = fmaf(bw.x, f6.x, a6); a6 = fmaf(bw.y, f6.y, a6);
        a6 = fmaf(bw.z, f6.z, a6); a6 = fmaf(bw.w, f6.w, a6);
        a7 = fmaf(bw.x, f7.x, a7); a7 = fmaf(bw.y, f7.y, a7);
        a7 = fmaf(bw.z, f7.z, a7); a7 = fmaf(bw.w, f7.w, a7);
    }

    // eight independent butterfly reductions (pipelined)
    #pragma unroll
    for (int o = 16; o; o >>= 1) {
        a0 += __shfl_xor_sync(0xffffffffu, a0, o);
        a1 += __shfl_xor_sync(0xffffffffu, a1, o);
        a2 += __shfl_xor_sync(0xffffffffu, a2, o);
        a3 += __shfl_xor_sync(0xffffffffu, a3, o);
        a4 += __shfl_xor_sync(0xffffffffu, a4, o);
        a5 += __shfl_xor_sync(0xffffffffu, a5, o);
        a6 += __shfl_xor_sync(0xffffffffu, a6, o);
        a7 += __shfl_xor_sync(0xffffffffu, a7, o);
    }
    if (lane == 0) {
        float* op = out + (size_t)roi * C_CH + c0;
        op[0]  = a0;
        op[8]  = a1;
        op[16] = a2;
        op[24] = a3;
        op[32] = a4;
        op[40] = a5;
        op[48] = a6;
        op[56] = a7;
    }
}

extern "C" void kernel_launch(void* const* d_in, const int* in_sizes, int n_in,
                              void* d_out, int out_size)
{
    const float* feat = (const float*)d_in[0];   // (4, 256, 128, 128) fp32
    const float* rois = (const float*)d_in[1];   // (N, 6) fp32
    float* out = (float*)d_out;

    const int n_rois = in_sizes[1] / 6;          // 512
    (void)n_in; (void)out_size;

    dim3 grid(n_rois, 4);
    roi_align_pool_kernel<<<grid, NTHREADS>>>(feat, rois, out, n_rois);
}